// round 9
// baseline (speedup 1.0000x reference)
#include <cuda_runtime.h>
#include <stdint.h>
#include <math.h>

#define NB    16384
#define NPRE  1024
#define NPOST 512
#define BATCH 2
#define NMS_THRESH 0.8f
#define NBINS 2048
#define QCAP  6144
#define GB_ROWS 64            // mask rows per block in k_mask
#define STAGE_CAP 316         // staged active rows (x32 words) in 40KB buffer

// ---------------- device scratch ----------------
__device__ int          g_topidx[BATCH][NPRE];
__device__ float        g_bev[BATCH][NPRE][16];
// per box: [0]x [1]y [2]dx [3]dy [4]cos [5]sin [6..9]cx [10..13]cy [14]area [15]radius
__device__ float4       g_prune[BATCH][NPRE];    // x, y, area, radius
__device__ unsigned int g_mask[BATCH][NPRE][32];
__device__ unsigned int g_rowAny[BATCH][32];
__device__ int          g_done[BATCH];

// ---------------- helpers ----------------
__device__ __forceinline__ unsigned fmap(float f) {
    unsigned u = __float_as_uint(f);
    return u ^ ((u & 0x80000000u) ? 0xFFFFFFFFu : 0x80000000u);
}

__device__ __forceinline__ unsigned long long ce_shfl(unsigned long long v, int i,
                                                      int stride, int size) {
    unsigned long long p = __shfl_xor_sync(0xffffffffu, v, stride);
    bool descB = ((i & size) == 0);
    bool lower = ((i & stride) == 0);
    bool keepMax = (descB == lower);
    unsigned long long mx = v > p ? v : p, mn = v > p ? p : v;
    return keepMax ? mx : mn;
}

// =====================================================================
// Kernel 1: top-1024 select + BEV (DP sincos only for selected).
// grid=BATCH, block=1024
// =====================================================================
__global__ void __launch_bounds__(1024, 1)
k_top(const float* __restrict__ cls, const float* __restrict__ boxes) {
    int b = blockIdx.x, t = threadIdx.x;
    __shared__ unsigned long long candA[2048];   // 16 KB
    __shared__ unsigned long long candB[2048];   // 16 KB (aliased: hist+cum early)
    unsigned* hist = (unsigned*)candB;           // [0..2048)
    unsigned* cum  = ((unsigned*)candB) + 2048;  // [2048..4096)
    __shared__ int s_b1, s_chi, s_b2, s_usel2, s_cnt;

    candA[t] = (unsigned long long)t;            // pad keys (unique, tiny)
    candA[t + 1024] = (unsigned long long)(t + 1024);
    hist[t] = 0u; hist[t + 1024] = 0u;
    if (t == 0) { s_usel2 = 0; s_cnt = 0; s_b2 = 0; g_done[b] = 0; }
    if (t < 32) g_rowAny[b][t] = 0u;
    __syncthreads();

    const float* C = cls + (size_t)b * NB * 3;

    // single pass: scores -> keys (registers) + histogram of top-11 bits
    unsigned myu[16];
#pragma unroll 4
    for (int k = 0; k < 16; k++) {
        int e = t + k * 1024;
        float s = fmaxf(fmaxf(C[e * 3], C[e * 3 + 1]), C[e * 3 + 2]);
        unsigned u = fmap(s);
        myu[k] = u;
        atomicAdd(&hist[u >> 21], 1u);
    }
    __syncthreads();

    // suffix scan: cum[i] = count of keys with bin >= i
    cum[t] = hist[t]; cum[t + 1024] = hist[t + 1024];
    __syncthreads();
    for (int off = 1; off < NBINS; off <<= 1) {
        unsigned v0 = (t + off < NBINS) ? cum[t + off] : 0u;
        unsigned v1 = (t + 1024 + off < NBINS) ? cum[t + 1024 + off] : 0u;
        __syncthreads();
        cum[t] += v0; cum[t + 1024] += v1;
        __syncthreads();
    }
    for (int i = t; i < NBINS; i += 1024) {
        if (cum[i] >= NPRE && (i == NBINS - 1 || cum[i + 1] < NPRE)) {
            s_b1 = i; s_chi = (i == NBINS - 1) ? 0 : (int)cum[i + 1];
        }
    }
    __syncthreads();
    int b1 = s_b1, chi = s_chi;
    int cnt1 = (int)cum[b1] - chi;

    if (chi + cnt1 > 2048) {      // rare: refine boundary bin by next 11 bits
        __syncthreads();
        hist[t] = 0u; hist[t + 1024] = 0u;
        if (t == 0) s_usel2 = 1;
        __syncthreads();
#pragma unroll 4
        for (int k = 0; k < 16; k++) {
            unsigned u = myu[k];
            if ((int)(u >> 21) == b1) atomicAdd(&hist[(u >> 10) & 0x7FF], 1u);
        }
        __syncthreads();
        cum[t] = hist[t]; cum[t + 1024] = hist[t + 1024];
        __syncthreads();
        for (int off = 1; off < NBINS; off <<= 1) {
            unsigned v0 = (t + off < NBINS) ? cum[t + off] : 0u;
            unsigned v1 = (t + 1024 + off < NBINS) ? cum[t + 1024 + off] : 0u;
            __syncthreads();
            cum[t] += v0; cum[t + 1024] += v1;
            __syncthreads();
        }
        int target2 = NPRE - chi;
        for (int i = t; i < NBINS; i += 1024) {
            if ((int)cum[i] >= target2 && (i == NBINS - 1 || (int)cum[i + 1] < target2))
                s_b2 = i;
        }
        __syncthreads();
    }

    // compact candidates into candA
    int usel2 = s_usel2, b2 = s_b2;
#pragma unroll 4
    for (int k = 0; k < 16; k++) {
        unsigned u = myu[k];
        int bin = (int)(u >> 21);
        bool take = (bin > b1) ||
                    (bin == b1 && (!usel2 || (int)((u >> 10) & 0x7FF) >= b2));
        if (take) {
            int p = atomicAdd(&s_cnt, 1);
            if (p < 2048) {
                int e = t + k * 1024;
                candA[p] = ((unsigned long long)u << 32) | (unsigned)(~(unsigned)e);
            }
        }
    }
    __syncthreads();

    // ---- sort phase 1: each warp sorts its 64-key chunk in registers (desc) ----
    {
        int w = t >> 5, l = t & 31;
        unsigned long long v0 = candA[w * 64 + l];
        unsigned long long v1 = candA[w * 64 + 32 + l];
        int i0 = l, i1 = l + 32;
#pragma unroll
        for (int size = 2; size <= 64; size <<= 1) {
#pragma unroll
            for (int stride = size >> 1; stride > 0; stride >>= 1) {
                if (stride == 32) {
                    bool descB = ((i0 & size) == 0);
                    unsigned long long mx = v0 > v1 ? v0 : v1;
                    unsigned long long mn = v0 > v1 ? v1 : v0;
                    v0 = descB ? mx : mn; v1 = descB ? mn : mx;
                } else {
                    v0 = ce_shfl(v0, i0, stride, size);
                    v1 = ce_shfl(v1, i1, stride, size);
                }
            }
        }
        candA[w * 64 + l] = v0;
        candA[w * 64 + 32 + l] = v1;
    }
    __syncthreads();

    // ---- sort phase 2: 5 merge rounds via binary search (32 runs -> 1) ----
    {
        unsigned long long* src = candA;
        unsigned long long* dst = candB;
#pragma unroll
        for (int r = 0; r < 5; r++) {
            int L = 64 << r;
#pragma unroll
            for (int h = 0; h < 2; h++) {
                int p = t + h * 1024;
                unsigned long long key = src[p];
                bool first = ((p & L) == 0);
                int pairBase = p & ~(2 * L - 1);
                int idxInRun = p & (L - 1);
                int otherBase = pairBase + (first ? L : 0);
                int lo = 0, hi = L;
                while (lo < hi) {
                    int mid = (lo + hi) >> 1;
                    if (src[otherBase + mid] > key) lo = mid + 1; else hi = mid;
                }
                dst[pairBase + idxInRun + lo] = key;
            }
            __syncthreads();
            unsigned long long* tmp = src; src = dst; dst = tmp;
        }
    }

    // ---- top-1024: indices + BEV geometry (DP sincos: 1 per thread) ----
    if (t < NPRE) {
        int sel = (int)(~(unsigned)(candB[t] & 0xFFFFFFFFULL));
        g_topidx[b][t] = sel;
        const float* p = boxes + (size_t)(b * NB + sel) * 7;
        float x = p[0], y = p[1], dx = p[3], dy = p[4], ry = p[6];
        float c = (float)cos((double)ry);
        float s = (float)sin((double)ry);
        float* o = g_bev[b][t];
        o[0] = x; o[1] = y; o[2] = dx; o[3] = dy; o[4] = c; o[5] = s;
        const float offx[4] = { 0.5f, -0.5f, -0.5f,  0.5f };
        const float offy[4] = { 0.5f,  0.5f, -0.5f, -0.5f };
#pragma unroll
        for (int q = 0; q < 4; q++) {
            float lx = dx * offx[q], ly = dy * offy[q];
            o[6 + q]  = x + lx * c - ly * s;
            o[10 + q] = y + lx * s + ly * c;
        }
        float area = dx * dy;
        float rad  = 0.5f * sqrtf(dx * dx + dy * dy);
        o[14] = area; o[15] = rad;
        g_prune[b][t] = make_float4(x, y, area, rad);
    }
}

// ---------------- faithful pairwise IoU (register-only) ----------------
__device__ float pair_iou(const float* __restrict__ A, const float* __restrict__ B) {
    float ax[4], ay[4], bx[4], by[4];
#pragma unroll
    for (int k = 0; k < 4; k++) { ax[k] = A[6 + k]; ay[k] = A[10 + k]; bx[k] = B[6 + k]; by[k] = B[10 + k]; }
    float dax[4], day[4], dbx[4], dby[4];
#pragma unroll
    for (int k = 0; k < 4; k++) {
        dax[k] = ax[(k + 1) & 3] - ax[k];  day[k] = ay[(k + 1) & 3] - ay[k];
        dbx[k] = bx[(k + 1) & 3] - bx[k];  dby[k] = by[(k + 1) & 3] - by[k];
    }
    float P[32], Q[32], ANG[32];
    bool mk[24];
#pragma unroll
    for (int p = 0; p < 4; p++) {
#pragma unroll
        for (int q = 0; q < 4; q++) {
            int id = p * 4 + q;
            float den = dax[p] * dby[q] - day[p] * dbx[q];
            float ddx = bx[q] - ax[p], ddy = by[q] - ay[p];
            bool nz = fabsf(den) > 1e-8f;
            float dens = nz ? den : 1.0f;
            float tt = (ddx * dby[q] - ddy * dbx[q]) / dens;
            float uu = (ddx * day[p] - ddy * dax[p]) / dens;
            mk[id] = nz && tt >= 0.f && tt <= 1.f && uu >= 0.f && uu <= 1.f;
            P[id] = ax[p] + tt * dax[p];
            Q[id] = ay[p] + tt * day[p];
        }
    }
    float Bx = B[0], By = B[1], Bdx = B[2], Bdy = B[3], Bc = B[4], Bs = B[5];
    float Ax = A[0], Ay = A[1], Adx = A[2], Ady = A[3], Ac = A[4], As = A[5];
#pragma unroll
    for (int k = 0; k < 4; k++) {
        P[16 + k] = ax[k]; Q[16 + k] = ay[k];
        float rx = ax[k] - Bx, ry = ay[k] - By;
        float qx = rx * Bc + ry * Bs, qy = -rx * Bs + ry * Bc;
        mk[16 + k] = (fabsf(qx) <= Bdx * 0.5f + 1e-5f) && (fabsf(qy) <= Bdy * 0.5f + 1e-5f);
        P[20 + k] = bx[k]; Q[20 + k] = by[k];
        float rx2 = bx[k] - Ax, ry2 = by[k] - Ay;
        float qx2 = rx2 * Ac + ry2 * As, qy2 = -rx2 * As + ry2 * Ac;
        mk[20 + k] = (fabsf(qx2) <= Adx * 0.5f + 1e-5f) && (fabsf(qy2) <= Ady * 0.5f + 1e-5f);
    }
    int cnt = 0; float sx = 0.f, sy = 0.f;
#pragma unroll
    for (int k = 0; k < 24; k++) if (mk[k]) { cnt++; sx += P[k]; sy += Q[k]; }
    float inv = 1.0f / (float)(cnt > 0 ? cnt : 1);
    float cx = sx * inv, cy = sy * inv;
#pragma unroll
    for (int k = 0; k < 24; k++)
        ANG[k] = mk[k] ? atan2f(Q[k] - cy, P[k] - cx) : 1e9f;
#pragma unroll
    for (int k = 24; k < 32; k++) { ANG[k] = 1e30f; P[k] = 0.f; Q[k] = 0.f; }
#pragma unroll
    for (int size = 2; size <= 32; size <<= 1) {
#pragma unroll
        for (int stride = size >> 1; stride > 0; stride >>= 1) {
#pragma unroll
            for (int i = 0; i < 32; i++) {
                int j = i ^ stride;
                if (j > i) {
                    bool up = ((i & size) == 0);
                    bool sw = up ? (ANG[i] > ANG[j]) : (ANG[i] < ANG[j]);
                    float t0 = sw ? ANG[j] : ANG[i]; float t1 = sw ? ANG[i] : ANG[j];
                    ANG[i] = t0; ANG[j] = t1;
                    float p0 = sw ? P[j] : P[i];     float p1 = sw ? P[i] : P[j];
                    P[i] = p0; P[j] = p1;
                    float q0 = sw ? Q[j] : Q[i];     float q1 = sw ? Q[i] : Q[j];
                    Q[i] = q0; Q[j] = q1;
                }
            }
        }
    }
    float fx = P[0], fy = Q[0];
    float cr = 0.f;
#pragma unroll
    for (int k = 0; k < 24; k++) {
        int kn = (k + 1) % 24;
        float xk = (k  < cnt) ? P[k]  : fx;
        float yk = (k  < cnt) ? Q[k]  : fy;
        float xn = (kn < cnt) ? P[kn] : fx;
        float yn = (kn < cnt) ? Q[kn] : fy;
        cr += xk * yn - yk * xn;
    }
    float inter = 0.5f * fabsf(cr);
    return inter / fmaxf(A[14] + B[14] - inter, 1e-6f);
}

// =====================================================================
// Kernel 2: prune + exact IoU -> bitmask + rowAny; LAST block per batch
// runs greedy NMS (smem-staged rows) + output write.
// grid = (NPRE/GB_ROWS, BATCH), block = 256
// =====================================================================
__global__ void __launch_bounds__(256, 1)
k_mask(const float* __restrict__ boxes, const float* __restrict__ cls,
       float* __restrict__ out) {
    int b = blockIdx.y, blk = blockIdx.x, t = threadIdx.x;
    int i0 = blk * GB_ROWS;
    __shared__ __align__(16) unsigned buf[10240];   // 40 KB multi-use
    float4*   spr = (float4*)buf;                   // prune vecs  [0..4096) uints
    unsigned* q   = buf + 4096;                     // pair queue  [4096..10240)
    __shared__ unsigned actList[NPRE];              // 4 KB (NMS phase)
    __shared__ int pos[NPOST];                      // 2 KB
    __shared__ unsigned s_rowAny[32];
    __shared__ unsigned baseArr[32];
    __shared__ int qc, s_nact;

    if (t == 0) qc = 0;
    for (int k = t; k < NPRE; k += 256) spr[k] = g_prune[b][k];
    for (int k = t; k < GB_ROWS * 32; k += 256)
        ((unsigned*)g_mask[b][i0])[k] = 0u;
    __syncthreads();

    float4 pj[4];
#pragma unroll
    for (int jj = 0; jj < 4; jj++) pj[jj] = spr[t + jj * 256];

    for (int r = 0; r < GB_ROWS; r++) {
        int i = i0 + r;
        float4 pi = spr[i];
#pragma unroll
        for (int jj = 0; jj < 4; jj++) {
            int j = t + jj * 256;
            if (j > i) {
                float ddx = pi.x - pj[jj].x, ddy = pi.y - pj[jj].y;
                float rs = pi.w + pj[jj].w + 1e-3f;
                if (ddx * ddx + ddy * ddy < rs * rs) {
                    float amin = fminf(pi.z, pj[jj].z), amax = fmaxf(pi.z, pj[jj].z);
                    if (amin > 0.79f * amax) {
                        int p = atomicAdd(&qc, 1);
                        if (p < QCAP) q[p] = ((unsigned)i << 16) | (unsigned)j;
                        else {  // overflow fallback (never expected)
                            float iou = pair_iou(g_bev[b][i], g_bev[b][j]);
                            if (iou > NMS_THRESH)
                                atomicOr(&g_mask[b][i][j >> 5], 1u << (j & 31));
                        }
                    }
                }
            }
        }
    }
    __syncthreads();
    int n = min(qc, QCAP);
    for (int p = t; p < n; p += 256) {
        unsigned pr = q[p];
        int i = (int)(pr >> 16), jj = (int)(pr & 0xFFFFu);
        float iou = pair_iou(g_bev[b][i], g_bev[b][jj]);
        if (iou > NMS_THRESH) atomicOr(&g_mask[b][i][jj >> 5], 1u << (jj & 31));
    }
    __syncthreads();
    // rowAny for this strip: 8 warps x 8 sweeps covers 64 rows
    {
        int lane = t & 31, w = t >> 5;
#pragma unroll
        for (int sweep = 0; sweep < 8; sweep++) {
            int row = i0 + sweep * 8 + w;
            unsigned val = g_mask[b][row][lane];
            bool any = __any_sync(0xffffffffu, val != 0u);
            if (lane == 0 && any)
                atomicOr(&g_rowAny[b][row >> 5], 1u << (row & 31));
        }
    }

    // -------- last-block election --------
    __threadfence();
    __syncthreads();
    __shared__ int s_last;
    if (t == 0) s_last = (atomicAdd(&g_done[b], 1) == (NPRE / GB_ROWS) - 1);
    __syncthreads();
    if (!s_last) return;
    __threadfence();   // acquire: see all blocks' mask/rowAny writes

    // -------- NMS phase (this block only) --------
    if (t < 32) s_rowAny[t] = g_rowAny[b][t];
    for (int k = t; k < NPOST; k += 256) pos[k] = -1;
    __syncthreads();
    if (t < 32) {
        int c = __popc(s_rowAny[t]);
        int ex = c;
        for (int o = 1; o < 32; o <<= 1) {
            int v = __shfl_up_sync(0xffffffffu, ex, o);
            if (t >= o) ex += v;
        }
        baseArr[t] = ex - c;                       // exclusive prefix
        if (t == 31) s_nact = ex;                  // total active rows
    }
    __syncthreads();
    int nact = s_nact;
    // build slot -> row list
    for (int row = t; row < NPRE; row += 256) {
        unsigned ra = s_rowAny[row >> 5];
        if ((ra >> (row & 31)) & 1u) {
            int slot = baseArr[row >> 5] + __popc(ra & ((1u << (row & 31)) - 1u));
            actList[slot] = row;
        }
    }
    __syncthreads();
    // stage active rows into buf (reused; 316 rows x 32 words)
    unsigned* stage = buf;
    int nst = min(nact, STAGE_CAP);
    for (int idx = t; idx < nst * 32; idx += 256)
        stage[idx] = g_mask[b][actList[idx >> 5]][idx & 31];
    __syncthreads();

    if (t < 32) {
        int lane = t;
        unsigned supp = 0u;
        const unsigned* __restrict__ M = &g_mask[b][0][0];
        for (int c = 0; c < 32; c++) {
            unsigned ra = s_rowAny[c];
            unsigned cur = __shfl_sync(0xffffffffu, supp, c);
            if (ra & ~cur) {
                unsigned base = baseArr[c];
                unsigned d[32];
#pragma unroll
                for (int k = 0; k < 32; k++) {
                    if ((ra >> k) & 1u) {
                        int slot = base + __popc(ra & ((1u << k) - 1u));
                        d[k] = (slot < STAGE_CAP) ? stage[slot * 32 + c]
                                                  : M[(c * 32 + k) * 32 + c];
                    } else d[k] = 0u;
                }
#pragma unroll
                for (int k = 0; k < 32; k++)
                    cur |= ((cur >> k) & 1u) ? 0u : d[k];
                unsigned act = ~cur & ra;
                while (act) {
                    int k = __ffs(act) - 1;
                    int slot = base + __popc(ra & ((1u << k) - 1u));
                    supp |= (slot < STAGE_CAP) ? stage[slot * 32 + lane]
                                               : M[(c * 32 + k) * 32 + lane];
                    act &= act - 1;
                }
            }
        }
        unsigned keep = ~supp;
        int cc = __popc(keep);
        int incl = cc;
        for (int o = 1; o < 32; o <<= 1) {
            int v = __shfl_up_sync(0xffffffffu, incl, o);
            if (lane >= o) incl += v;
        }
        int excl = incl - cc;
        __syncwarp();
        unsigned m = keep;
        int slot = excl;
        while (m) {
            if (slot >= NPOST) break;
            int bit = __ffs(m) - 1;
            pos[slot++] = lane * 32 + bit;
            m &= (m - 1);
        }
    }
    __syncthreads();

    // -------- output write (256 threads x 2) --------
    for (int k = t; k < NPOST; k += 256) {
        int p = pos[k];
        float r0 = 0.f, r1 = 0.f, r2 = 0.f, r3 = 0.f, r4 = 0.f, r5 = 0.f, r6 = 0.f;
        float l0 = 0.f, l1 = 0.f, l2 = 0.f, score = 0.f, lab = 1.f;
        if (p >= 0) {
            int sel = g_topidx[b][p];
            const float* bp = boxes + (size_t)(b * NB + sel) * 7;
            r0 = bp[0]; r1 = bp[1]; r2 = bp[2]; r3 = bp[3]; r4 = bp[4]; r5 = bp[5]; r6 = bp[6];
            const float* cp = cls + (size_t)(b * NB + sel) * 3;
            l0 = cp[0]; l1 = cp[1]; l2 = cp[2];
            int a = 0; float best = l0;
            if (l1 > best) { best = l1; a = 1; }
            if (l2 > best) { best = l2; a = 2; }
            score = best; lab = (float)(a + 1);
        }
        int s = b * NPOST + k;
        float* ro = out + (size_t)s * 7;
        ro[0] = r0; ro[1] = r1; ro[2] = r2; ro[3] = r3; ro[4] = r4; ro[5] = r5; ro[6] = r6;
        out[BATCH * NPOST * 7 + s] = score;
        out[BATCH * NPOST * 8 + s] = lab;
        float* lo = out + BATCH * NPOST * 9 + (size_t)s * 3;
        lo[0] = l0; lo[1] = l1; lo[2] = l2;
    }
}

// ---------------- launch ----------------
extern "C" void kernel_launch(void* const* d_in, const int* in_sizes, int n_in,
                              void* d_out, int out_size) {
    const float* boxes = (const float*)d_in[0];
    const float* cls   = (const float*)d_in[1];
    if (n_in >= 2 && in_sizes[0] == BATCH * NB * 3) {
        const float* tmp = boxes; boxes = cls; cls = tmp;
    }
    float* out = (float*)d_out;
    (void)out_size;

    k_top <<<BATCH, 1024>>>(cls, boxes);
    k_mask<<<dim3(NPRE / GB_ROWS, BATCH), 256>>>(boxes, cls, out);
}